// round 16
// baseline (speedup 1.0000x reference)
#include <cuda_runtime.h>
#include <cuda_bf16.h>
#include <math.h>

#define N_NODES 8192
#define EMBED   64
#define HID0    256
#define HID1    256
#define HID2    128
#define ACTION  8192
#define IN_SIZE (N_NODES + EMBED)   // 8256
#define ROW_F4  (IN_SIZE / 4)       // 2064
#define RPB 8
#define NGROUPS 2
#define MV_BLOCKS (N_NODES / RPB / NGROUPS)   // 512
#define TREP 4
#define FC3_BLOCKS 16

#if defined(__CUDA_ARCH__) && (__CUDA_ARCH__ >= 900)
#define PDL_TRIGGER()  cudaTriggerProgrammaticLaunchCompletion()
#define PDL_WAIT()     cudaGridDependencySynchronize()
#else
#define PDL_TRIGGER()
#define PDL_WAIT()
#endif

// ---- scratch ----
__device__ float g_x[N_NODES];
__device__ float g_t_rep[TREP][HID0];
__device__ float g_fc1p[HID0];
__device__ float g_y1[HID0];
__device__ float g_y2[HID1];
__device__ float g_y3[HID2];
__device__ unsigned int g_ctr3;      // fc3-done counter (16 producers)

// K1: extract diagonal + zero t replicas + reset fc3 counter
__global__ void k_diag(const float* __restrict__ state) {
    PDL_TRIGGER();
    int i = blockIdx.x * blockDim.x + threadIdx.x;
    if (i == 0) g_ctr3 = 0u;
    if (i < TREP * HID0) ((float*)g_t_rep)[i] = 0.0f;
    if (i < N_NODES) g_x[i] = state[(size_t)i * (N_NODES + 1)];
}

// K2: blocks [0,512): matvec — 2 sequential row-groups of 8 rows (single wave)
//     blocks [512,768): fc1 partials (independent -> overlap diag)
__global__ void __launch_bounds__(256) k_matvec_fc1p(const float* __restrict__ state,
                                                     const int* __restrict__ start_p,
                                                     const float* __restrict__ gc1_w,
                                                     const float* __restrict__ gc1_b,
                                                     const float* __restrict__ fc1_w) {
    PDL_TRIGGER();
    int tid = threadIdx.x;
    if (blockIdx.x < MV_BLOCKS) {
        float wj = gc1_w[tid];
        float bj = gc1_b[tid];
        int st = *start_p;

        PDL_WAIT();   // need g_x + zeroed g_t_rep

        int lane = tid & 31, wid = tid >> 5;
        __shared__ float sh[RPB][8];
        __shared__ float s_sh[RPB];
        __shared__ float a_sh[RPB];
        const float4* __restrict__ xp = (const float4*)g_x;
        float ct = 0.0f;

        #pragma unroll
        for (int g = 0; g < NGROUPS; g++) {
            int r0 = (blockIdx.x + g * MV_BLOCKS) * RPB;
            const float4* __restrict__ base =
                (const float4*)(state + (size_t)r0 * N_NODES);
            float acc[RPB];
            #pragma unroll
            for (int r = 0; r < RPB; r++) acc[r] = 0.0f;
            for (int j = tid; j < N_NODES / 4; j += 256) {
                float4 xv = xp[j];
                #pragma unroll
                for (int r = 0; r < RPB; r++) {
                    float4 a = __ldcs(&base[(size_t)r * (N_NODES / 4) + j]);
                    acc[r] += a.x * xv.x + a.y * xv.y + a.z * xv.z + a.w * xv.w;
                }
            }
            #pragma unroll
            for (int r = 0; r < RPB; r++)
                #pragma unroll
                for (int o = 16; o; o >>= 1)
                    acc[r] += __shfl_down_sync(0xffffffffu, acc[r], o);
            __syncthreads();
            if (lane == 0) {
                #pragma unroll
                for (int r = 0; r < RPB; r++) sh[r][wid] = acc[r];
            }
            __syncthreads();
            if (tid < RPB * 8) {
                int r = tid >> 3, w = tid & 7;
                float v = sh[r][w];
                v += __shfl_down_sync(0xffffffffu, v, 4, 8);
                v += __shfl_down_sync(0xffffffffu, v, 2, 8);
                v += __shfl_down_sync(0xffffffffu, v, 1, 8);
                if (w == 0) {
                    int row = r0 + r;
                    float xi = g_x[row];
                    s_sh[r] = v - xi * xi;
                    a_sh[r] = (row == st) ? 0.0f : state[(size_t)st * N_NODES + row];
                }
            }
            __syncthreads();
            #pragma unroll
            for (int r = 0; r < RPB; r++)
                ct += a_sh[r] * fmaxf(fmaf(s_sh[r], wj, bj), 0.0f);
        }
        atomicAdd(&g_t_rep[blockIdx.x & (TREP - 1)][tid], ct);
    } else {
        int r = blockIdx.x - MV_BLOCKS;
        int st = *start_p;
        const float4* __restrict__ w4 = (const float4*)(fc1_w + (size_t)r * IN_SIZE);
        const float4* __restrict__ s4 = (const float4*)(state + (size_t)st * N_NODES);
        float acc = 0.0f;
        #pragma unroll 8
        for (int j = tid; j < N_NODES / 4; j += 256) {
            float4 a = __ldcs(&w4[j]);
            float4 b = s4[j];
            acc += a.x * b.x + a.y * b.y + a.z * b.z + a.w * b.w;
        }
        int lane = tid & 31, wid = tid >> 5;
        #pragma unroll
        for (int o = 16; o; o >>= 1) acc += __shfl_down_sync(0xffffffffu, acc, o);
        __shared__ float sh2[8];
        if (lane == 0) sh2[wid] = acc;
        __syncthreads();
        if (tid < 8) {
            float v = sh2[tid];
            v += __shfl_down_sync(0xffu, v, 4, 8);
            v += __shfl_down_sync(0xffu, v, 2, 8);
            v += __shfl_down_sync(0xffu, v, 1, 8);
            if (tid == 0) g_fc1p[r] = v;
        }
    }
}

// K3 (1 block, 1024 threads, dynamic smem): preload gc2_w + fc1 tail + biases
// pre-gate; then emb -> softmax -> fc1 finish. Gates directly on matvec.
__global__ void __launch_bounds__(1024) k_emb_fc1(const float* __restrict__ gc2_w,
                                                  const float* __restrict__ gc2_b,
                                                  const float* __restrict__ fc1_w,
                                                  const float* __restrict__ fc1_b) {
    PDL_TRIGGER();
    extern __shared__ float dyn[];
    float* sm_gc2  = dyn;                       // 16384 floats (gc2_w, [j][c])
    float* sm_fc1t = dyn + HID0 * EMBED;        // 16384 floats ([r][64])
    float* sm_fc1b = sm_fc1t + HID0 * EMBED;    // 256
    float* sm_gc2b = sm_fc1b + HID0;            // 64

    __shared__ float ts[HID0];
    __shared__ float part[16][EMBED];
    __shared__ float hv[EMBED];
    __shared__ float emb[EMBED];
    __shared__ float red[1];
    int tid = threadIdx.x;

    // ---- pre-gate weight staging (overlaps matvec) ----
    {
        const float4* __restrict__ src = (const float4*)gc2_w;
        float4* dst = (float4*)sm_gc2;
        for (int i = tid; i < HID0 * EMBED / 4; i += 1024) dst[i] = src[i];
        const float4* __restrict__ w4 = (const float4*)fc1_w;
        float4* dst2 = (float4*)sm_fc1t;
        for (int i = tid; i < HID0 * 16; i += 1024) {
            int r = i >> 4, c = i & 15;
            dst2[i] = w4[(size_t)r * ROW_F4 + (N_NODES / 4) + c];
        }
        if (tid < HID0) sm_fc1b[tid] = fc1_b[tid];
        if (tid < EMBED) sm_gc2b[tid] = gc2_b[tid];
    }
    __syncthreads();

    PDL_WAIT();   // need g_t_rep, g_fc1p (matvec grid complete)

    if (tid < HID0)
        ts[tid] = g_t_rep[0][tid] + g_t_rep[1][tid] + g_t_rep[2][tid] + g_t_rep[3][tid];
    __syncthreads();

    // Stage A: u[c] = sum_j ts[j] * gc2[j,c], 16 partials
    {
        int c = tid & 63, p = tid >> 6;
        float u = 0.0f;
        #pragma unroll
        for (int j = p * 16; j < p * 16 + 16; j++)
            u = fmaf(ts[j], sm_gc2[j * EMBED + c], u);
        part[p][c] = u;
    }
    __syncthreads();
    if (tid < EMBED) {
        float h = 0.0f;
        #pragma unroll
        for (int q = 0; q < 16; q++) h += part[q][tid];
        hv[tid] = fmaxf(h + sm_gc2b[tid], 0.0f);
    }
    __syncthreads();
    if (tid < 32) {
        float m = fmaxf(hv[tid], hv[tid + 32]);
        #pragma unroll
        for (int o = 16; o; o >>= 1) m = fmaxf(m, __shfl_xor_sync(0xffffffffu, m, o));
        float s = expf(hv[tid] - m) + expf(hv[tid + 32] - m);
        #pragma unroll
        for (int o = 16; o; o >>= 1) s += __shfl_xor_sync(0xffffffffu, s, o);
        if (tid == 0) red[0] = m + logf(s);
    }
    __syncthreads();
    if (tid < EMBED) emb[tid] = hv[tid] - red[0];
    __syncthreads();

    // fc1 finish from smem — 4 threads per row.
    {
        int r = tid >> 2, q = tid & 3;
        const float4* __restrict__ w4 = (const float4*)(sm_fc1t + r * EMBED);
        const float4* __restrict__ e4 = (const float4*)emb;
        float acc = 0.0f;
        #pragma unroll
        for (int i = 0; i < 4; i++) {
            float4 w = w4[q * 4 + i];
            float4 e = e4[q * 4 + i];
            acc += w.x * e.x + w.y * e.y + w.z * e.z + w.w * e.w;
        }
        acc += __shfl_down_sync(0xffffffffu, acc, 2, 4);
        acc += __shfl_down_sync(0xffffffffu, acc, 1, 4);
        if (q == 0) g_y1[r] = fmaxf(acc + g_fc1p[r] + sm_fc1b[r], 0.0f);
    }
}

// K4: fc2 — warp per output; weights preloaded to regs pre-gate.
__global__ void __launch_bounds__(256) k_fc2(const float* __restrict__ fc2_w,
                                             const float* __restrict__ fc2_b) {
    PDL_TRIGGER();
    int tid = threadIdx.x, warp = tid >> 5, lane = tid & 31;
    int o = blockIdx.x * 8 + warp;
    const float4* __restrict__ w4 = (const float4*)(fc2_w + (size_t)o * HID0);
    float4 wa = w4[lane], wb = w4[lane + 32];
    float b = fc2_b[o];
    PDL_WAIT();   // need g_y1
    const float4* __restrict__ y4 = (const float4*)g_y1;
    float4 ya = y4[lane], yb = y4[lane + 32];
    float acc = wa.x * ya.x + wa.y * ya.y + wa.z * ya.z + wa.w * ya.w +
                wb.x * yb.x + wb.y * yb.y + wb.z * yb.z + wb.w * yb.w;
    #pragma unroll
    for (int off = 16; off; off >>= 1) acc += __shfl_down_sync(0xffffffffu, acc, off);
    if (lane == 0) g_y2[o] = fmaxf(acc + b, 0.0f);
}

// K5: fc3 + fc4 merged.
//   blocks [0,16): fc3 — warp per output, weights preloaded pre-gate,
//                  PDL_WAIT on fc2, write y3, fence, bump counter.
//   blocks [16,1040): fc4 — weights preloaded pre-gate, PDL_WAIT (so polling
//                  never overlaps earlier kernels), then volatile-poll ctr==16,
//                  read y3, finish.
__global__ void __launch_bounds__(256) k_fc34(const float* __restrict__ fc3_w,
                                              const float* __restrict__ fc3_b,
                                              const float* __restrict__ fc4_w,
                                              const float* __restrict__ fc4_b,
                                              float* __restrict__ out) {
    PDL_TRIGGER();
    int tid = threadIdx.x, warp = tid >> 5, lane = tid & 31;
    if (blockIdx.x < FC3_BLOCKS) {
        int o = blockIdx.x * 8 + warp;
        const float4* __restrict__ w4 = (const float4*)(fc3_w + (size_t)o * HID1);
        float4 wa = w4[lane], wb = w4[lane + 32];
        float b = fc3_b[o];
        PDL_WAIT();   // need g_y2
        const float4* __restrict__ y4 = (const float4*)g_y2;
        float4 ya = y4[lane], yb = y4[lane + 32];
        float acc = wa.x * ya.x + wa.y * ya.y + wa.z * ya.z + wa.w * ya.w +
                    wb.x * yb.x + wb.y * yb.y + wb.z * yb.z + wb.w * yb.w;
        #pragma unroll
        for (int off = 16; off; off >>= 1) acc += __shfl_down_sync(0xffffffffu, acc, off);
        if (lane == 0) g_y3[o] = fmaxf(acc + b, 0.0f);
        __syncthreads();
        if (tid == 0) { __threadfence(); atomicAdd(&g_ctr3, 1u); }
    } else {
        int a = (blockIdx.x - FC3_BLOCKS) * 8 + warp;
        float4 w = ((const float4*)(fc4_w + (size_t)a * HID2))[lane];
        float b = fc4_b[a];
        PDL_WAIT();   // gate on fc2 first: polling below spans only fc3 (~1us)
        if (tid == 0) {
            volatile unsigned int* c = &g_ctr3;
            while (*c < FC3_BLOCKS) __nanosleep(128);
        }
        __syncthreads();
        __threadfence();
        const float4* __restrict__ y4 = (const float4*)g_y3;
        float4 y = __ldcg(&y4[lane]);
        float acc = w.x * y.x + w.y * y.y + w.z * y.z + w.w * y.w;
        #pragma unroll
        for (int o = 16; o; o >>= 1) acc += __shfl_down_sync(0xffffffffu, acc, o);
        if (lane == 0) out[a] = fmaxf(acc + b, 0.0f);
    }
}

// ---- host launch helper ----
template <typename... Args>
static inline void launch_pdl(void (*kern)(Args...), dim3 grid, dim3 block,
                              unsigned smem, Args... args) {
    cudaLaunchConfig_t cfg = {};
    cfg.gridDim = grid;
    cfg.blockDim = block;
    cfg.dynamicSmemBytes = smem;
    cfg.stream = 0;
    cudaLaunchAttribute attr[1];
    attr[0].id = cudaLaunchAttributeProgrammaticStreamSerialization;
    attr[0].val.programmaticStreamSerializationAllowed = 1;
    cfg.attrs = attr;
    cfg.numAttrs = 1;
    cudaLaunchKernelEx(&cfg, kern, args...);
}

extern "C" void kernel_launch(void* const* d_in, const int* in_sizes, int n_in,
                              void* d_out, int out_size) {
    const float* state = (const float*)d_in[0];
    const int*   start = (const int*)d_in[1];
    const float* gc1_w = (const float*)d_in[2];
    const float* gc1_b = (const float*)d_in[3];
    const float* gc2_w = (const float*)d_in[4];
    const float* gc2_b = (const float*)d_in[5];
    const float* fc1_w = (const float*)d_in[6];
    const float* fc1_b = (const float*)d_in[7];
    const float* fc2_w = (const float*)d_in[8];
    const float* fc2_b = (const float*)d_in[9];
    const float* fc3_w = (const float*)d_in[10];
    const float* fc3_b = (const float*)d_in[11];
    const float* fc4_w = (const float*)d_in[12];
    const float* fc4_b = (const float*)d_in[13];
    float* out = (float*)d_out;

    const unsigned EMB_SMEM = (HID0 * EMBED * 2 + HID0 + EMBED) * sizeof(float);
    static bool attr_set = false;
    if (!attr_set) {
        cudaFuncSetAttribute(k_emb_fc1, cudaFuncAttributeMaxDynamicSharedMemorySize,
                             EMB_SMEM);
        attr_set = true;
    }

    k_diag<<<N_NODES / 256, 256>>>(state);
    launch_pdl(k_matvec_fc1p, dim3(MV_BLOCKS + HID0), dim3(256), 0u,
               state, start, gc1_w, gc1_b, fc1_w);
    launch_pdl(k_emb_fc1, dim3(1), dim3(1024), EMB_SMEM,
               gc2_w, gc2_b, fc1_w, fc1_b);
    launch_pdl(k_fc2, dim3(HID1 / 8), dim3(256), 0u, fc2_w, fc2_b);
    launch_pdl(k_fc34, dim3(FC3_BLOCKS + ACTION / 8), dim3(256), 0u,
               fc3_w, fc3_b, fc4_w, fc4_b, out);
}

// round 17
// speedup vs baseline: 1.0457x; 1.0457x over previous
#include <cuda_runtime.h>
#include <cuda_bf16.h>
#include <math.h>

#define N_NODES 8192
#define EMBED   64
#define HID0    256
#define HID1    256
#define HID2    128
#define ACTION  8192
#define IN_SIZE (N_NODES + EMBED)   // 8256
#define ROW_F4  (IN_SIZE / 4)       // 2064
#define RPB 8
#define NGROUPS 2                    // row-groups per matvec block (sequential)
#define MV_BLOCKS (N_NODES / RPB / NGROUPS)   // 512
#define TREP 4                       // g_t replicas to spread atomic contention

#if defined(__CUDA_ARCH__) && (__CUDA_ARCH__ >= 900)
#define PDL_TRIGGER()  cudaTriggerProgrammaticLaunchCompletion()
#define PDL_WAIT()     cudaGridDependencySynchronize()
#else
#define PDL_TRIGGER()
#define PDL_WAIT()
#endif

// ---- scratch ----
__device__ float g_x[N_NODES];
__device__ float g_t_rep[TREP][HID0];
__device__ float g_fc1p[HID0];
__device__ float g_y1[HID0];
__device__ float g_y2[HID1];
__device__ float g_y3[HID2];

// K1: extract diagonal + zero t replicas
__global__ void k_diag(const float* __restrict__ state) {
    PDL_TRIGGER();
    int i = blockIdx.x * blockDim.x + threadIdx.x;
    if (i < TREP * HID0) ((float*)g_t_rep)[i] = 0.0f;
    if (i < N_NODES) g_x[i] = state[(size_t)i * (N_NODES + 1)];
}

// K2: blocks [0,512): matvec — 2 sequential row-groups of 8 rows each
//     (single wave; no wave-2 tail). Accumulates t contribution across both.
//     blocks [512,768): fc1 partials (independent -> overlap diag)
__global__ void __launch_bounds__(256) k_matvec_fc1p(const float* __restrict__ state,
                                                     const int* __restrict__ start_p,
                                                     const float* __restrict__ gc1_w,
                                                     const float* __restrict__ gc1_b,
                                                     const float* __restrict__ fc1_w) {
    PDL_TRIGGER();
    int tid = threadIdx.x;
    if (blockIdx.x < MV_BLOCKS) {
        // pre-gate loads (inputs only)
        float wj = gc1_w[tid];
        float bj = gc1_b[tid];
        int st = *start_p;

        PDL_WAIT();   // need g_x + zeroed g_t_rep

        int lane = tid & 31, wid = tid >> 5;
        __shared__ float sh[RPB][8];
        __shared__ float s_sh[RPB];
        __shared__ float a_sh[RPB];
        const float4* __restrict__ xp = (const float4*)g_x;
        float ct = 0.0f;   // t contribution accumulated over both groups

        #pragma unroll
        for (int g = 0; g < NGROUPS; g++) {
            int r0 = (blockIdx.x + g * MV_BLOCKS) * RPB;
            const float4* __restrict__ base =
                (const float4*)(state + (size_t)r0 * N_NODES);
            float acc[RPB];
            #pragma unroll
            for (int r = 0; r < RPB; r++) acc[r] = 0.0f;
            for (int j = tid; j < N_NODES / 4; j += 256) {
                float4 xv = xp[j];
                #pragma unroll
                for (int r = 0; r < RPB; r++) {
                    float4 a = __ldcs(&base[(size_t)r * (N_NODES / 4) + j]);
                    acc[r] += a.x * xv.x + a.y * xv.y + a.z * xv.z + a.w * xv.w;
                }
            }
            #pragma unroll
            for (int r = 0; r < RPB; r++)
                #pragma unroll
                for (int o = 16; o; o >>= 1)
                    acc[r] += __shfl_down_sync(0xffffffffu, acc[r], o);
            __syncthreads();   // protect sh/s_sh/a_sh reuse across groups
            if (lane == 0) {
                #pragma unroll
                for (int r = 0; r < RPB; r++) sh[r][wid] = acc[r];
            }
            __syncthreads();
            if (tid < RPB * 8) {
                int r = tid >> 3, w = tid & 7;
                float v = sh[r][w];
                v += __shfl_down_sync(0xffffffffu, v, 4, 8);
                v += __shfl_down_sync(0xffffffffu, v, 2, 8);
                v += __shfl_down_sync(0xffffffffu, v, 1, 8);
                if (w == 0) {
                    int row = r0 + r;
                    float xi = g_x[row];
                    s_sh[r] = v - xi * xi;
                    a_sh[r] = (row == st) ? 0.0f : state[(size_t)st * N_NODES + row];
                }
            }
            __syncthreads();
            #pragma unroll
            for (int r = 0; r < RPB; r++)
                ct += a_sh[r] * fmaxf(fmaf(s_sh[r], wj, bj), 0.0f);
        }
        atomicAdd(&g_t_rep[blockIdx.x & (TREP - 1)][tid], ct);
    } else {
        // fc1 partial: one block per output row r (independent of diag)
        int r = blockIdx.x - MV_BLOCKS;
        int st = *start_p;
        const float4* __restrict__ w4 = (const float4*)(fc1_w + (size_t)r * IN_SIZE);
        const float4* __restrict__ s4 = (const float4*)(state + (size_t)st * N_NODES);
        float acc = 0.0f;
        #pragma unroll 8
        for (int j = tid; j < N_NODES / 4; j += 256) {
            float4 a = __ldcs(&w4[j]);
            float4 b = s4[j];
            acc += a.x * b.x + a.y * b.y + a.z * b.z + a.w * b.w;
        }
        int lane = tid & 31, wid = tid >> 5;
        #pragma unroll
        for (int o = 16; o; o >>= 1) acc += __shfl_down_sync(0xffffffffu, acc, o);
        __shared__ float sh2[8];
        if (lane == 0) sh2[wid] = acc;
        __syncthreads();
        if (tid < 8) {
            float v = sh2[tid];
            v += __shfl_down_sync(0xffu, v, 4, 8);
            v += __shfl_down_sync(0xffu, v, 2, 8);
            v += __shfl_down_sync(0xffu, v, 1, 8);
            if (tid == 0) g_fc1p[r] = v;
        }
    }
}

// K3 (1 block, 1024 threads, dynamic smem): preload gc2_w + fc1 tail + biases
// pre-gate; then emb -> softmax -> fc1 finish. Gates directly on matvec.
__global__ void __launch_bounds__(1024) k_emb_fc1(const float* __restrict__ gc2_w,
                                                  const float* __restrict__ gc2_b,
                                                  const float* __restrict__ fc1_w,
                                                  const float* __restrict__ fc1_b) {
    PDL_TRIGGER();
    extern __shared__ float dyn[];
    float* sm_gc2  = dyn;                       // 16384 floats (gc2_w, [j][c])
    float* sm_fc1t = dyn + HID0 * EMBED;        // 16384 floats ([r][64])
    float* sm_fc1b = sm_fc1t + HID0 * EMBED;    // 256
    float* sm_gc2b = sm_fc1b + HID0;            // 64

    __shared__ float ts[HID0];
    __shared__ float part[16][EMBED];
    __shared__ float hv[EMBED];
    __shared__ float emb[EMBED];
    __shared__ float red[1];
    int tid = threadIdx.x;

    // ---- pre-gate weight staging (overlaps matvec) ----
    {
        const float4* __restrict__ src = (const float4*)gc2_w;
        float4* dst = (float4*)sm_gc2;
        for (int i = tid; i < HID0 * EMBED / 4; i += 1024) dst[i] = src[i];
        const float4* __restrict__ w4 = (const float4*)fc1_w;
        float4* dst2 = (float4*)sm_fc1t;
        for (int i = tid; i < HID0 * 16; i += 1024) {
            int r = i >> 4, c = i & 15;
            dst2[i] = w4[(size_t)r * ROW_F4 + (N_NODES / 4) + c];
        }
        if (tid < HID0) sm_fc1b[tid] = fc1_b[tid];
        if (tid < EMBED) sm_gc2b[tid] = gc2_b[tid];
    }
    __syncthreads();

    PDL_WAIT();   // need g_t_rep, g_fc1p (matvec grid complete)

    if (tid < HID0)
        ts[tid] = g_t_rep[0][tid] + g_t_rep[1][tid] + g_t_rep[2][tid] + g_t_rep[3][tid];
    __syncthreads();

    // Stage A: u[c] = sum_j ts[j] * gc2[j,c], 16 partials
    {
        int c = tid & 63, p = tid >> 6;
        float u = 0.0f;
        #pragma unroll
        for (int j = p * 16; j < p * 16 + 16; j++)
            u = fmaf(ts[j], sm_gc2[j * EMBED + c], u);
        part[p][c] = u;
    }
    __syncthreads();
    if (tid < EMBED) {
        float h = 0.0f;
        #pragma unroll
        for (int q = 0; q < 16; q++) h += part[q][tid];
        hv[tid] = fmaxf(h + sm_gc2b[tid], 0.0f);
    }
    __syncthreads();
    if (tid < 32) {
        float m = fmaxf(hv[tid], hv[tid + 32]);
        #pragma unroll
        for (int o = 16; o; o >>= 1) m = fmaxf(m, __shfl_xor_sync(0xffffffffu, m, o));
        float s = expf(hv[tid] - m) + expf(hv[tid + 32] - m);
        #pragma unroll
        for (int o = 16; o; o >>= 1) s += __shfl_xor_sync(0xffffffffu, s, o);
        if (tid == 0) red[0] = m + logf(s);
    }
    __syncthreads();
    if (tid < EMBED) emb[tid] = hv[tid] - red[0];
    __syncthreads();

    // fc1 finish from smem — 4 threads per row.
    {
        int r = tid >> 2, q = tid & 3;
        const float4* __restrict__ w4 = (const float4*)(sm_fc1t + r * EMBED);
        const float4* __restrict__ e4 = (const float4*)emb;
        float acc = 0.0f;
        #pragma unroll
        for (int i = 0; i < 4; i++) {
            float4 w = w4[q * 4 + i];
            float4 e = e4[q * 4 + i];
            acc += w.x * e.x + w.y * e.y + w.z * e.z + w.w * e.w;
        }
        acc += __shfl_down_sync(0xffffffffu, acc, 2, 4);
        acc += __shfl_down_sync(0xffffffffu, acc, 1, 4);
        if (q == 0) g_y1[r] = fmaxf(acc + g_fc1p[r] + sm_fc1b[r], 0.0f);
    }
}

// K4: fc2 — warp per output; weights preloaded to regs pre-gate.
__global__ void __launch_bounds__(256) k_fc2(const float* __restrict__ fc2_w,
                                             const float* __restrict__ fc2_b) {
    PDL_TRIGGER();
    int tid = threadIdx.x, warp = tid >> 5, lane = tid & 31;
    int o = blockIdx.x * 8 + warp;
    const float4* __restrict__ w4 = (const float4*)(fc2_w + (size_t)o * HID0);
    float4 wa = w4[lane], wb = w4[lane + 32];
    float b = fc2_b[o];
    PDL_WAIT();   // need g_y1
    const float4* __restrict__ y4 = (const float4*)g_y1;
    float4 ya = y4[lane], yb = y4[lane + 32];
    float acc = wa.x * ya.x + wa.y * ya.y + wa.z * ya.z + wa.w * ya.w +
                wb.x * yb.x + wb.y * yb.y + wb.z * yb.z + wb.w * yb.w;
    #pragma unroll
    for (int off = 16; off; off >>= 1) acc += __shfl_down_sync(0xffffffffu, acc, off);
    if (lane == 0) g_y2[o] = fmaxf(acc + b, 0.0f);
}

// K5: fc3 — warp per output; weights preloaded pre-gate.
__global__ void __launch_bounds__(256) k_fc3(const float* __restrict__ fc3_w,
                                             const float* __restrict__ fc3_b) {
    PDL_TRIGGER();
    int tid = threadIdx.x, warp = tid >> 5, lane = tid & 31;
    int o = blockIdx.x * 8 + warp;
    const float4* __restrict__ w4 = (const float4*)(fc3_w + (size_t)o * HID1);
    float4 wa = w4[lane], wb = w4[lane + 32];
    float b = fc3_b[o];
    PDL_WAIT();   // need g_y2
    const float4* __restrict__ y4 = (const float4*)g_y2;
    float4 ya = y4[lane], yb = y4[lane + 32];
    float acc = wa.x * ya.x + wa.y * ya.y + wa.z * ya.z + wa.w * ya.w +
                wb.x * yb.x + wb.y * yb.y + wb.z * yb.z + wb.w * yb.w;
    #pragma unroll
    for (int off = 16; off; off >>= 1) acc += __shfl_down_sync(0xffffffffu, acc, off);
    if (lane == 0) g_y3[o] = fmaxf(acc + b, 0.0f);
}

// K6: fc4 — warp per output; weights preloaded pre-gate.
__global__ void __launch_bounds__(256) k_fc4(const float* __restrict__ fc4_w,
                                             const float* __restrict__ fc4_b,
                                             float* __restrict__ out) {
    int tid = threadIdx.x, warp = tid >> 5, lane = tid & 31;
    int a = blockIdx.x * 8 + warp;
    float4 w = ((const float4*)(fc4_w + (size_t)a * HID2))[lane];
    float b = fc4_b[a];
    PDL_WAIT();   // need g_y3
    float4 y = ((const float4*)g_y3)[lane];
    float acc = w.x * y.x + w.y * y.y + w.z * y.z + w.w * y.w;
    #pragma unroll
    for (int o = 16; o; o >>= 1) acc += __shfl_down_sync(0xffffffffu, acc, o);
    if (lane == 0) out[a] = fmaxf(acc + b, 0.0f);
}

// ---- host launch helper ----
template <typename... Args>
static inline void launch_pdl(void (*kern)(Args...), dim3 grid, dim3 block,
                              unsigned smem, Args... args) {
    cudaLaunchConfig_t cfg = {};
    cfg.gridDim = grid;
    cfg.blockDim = block;
    cfg.dynamicSmemBytes = smem;
    cfg.stream = 0;
    cudaLaunchAttribute attr[1];
    attr[0].id = cudaLaunchAttributeProgrammaticStreamSerialization;
    attr[0].val.programmaticStreamSerializationAllowed = 1;
    cfg.attrs = attr;
    cfg.numAttrs = 1;
    cudaLaunchKernelEx(&cfg, kern, args...);
}

extern "C" void kernel_launch(void* const* d_in, const int* in_sizes, int n_in,
                              void* d_out, int out_size) {
    const float* state = (const float*)d_in[0];
    const int*   start = (const int*)d_in[1];
    const float* gc1_w = (const float*)d_in[2];
    const float* gc1_b = (const float*)d_in[3];
    const float* gc2_w = (const float*)d_in[4];
    const float* gc2_b = (const float*)d_in[5];
    const float* fc1_w = (const float*)d_in[6];
    const float* fc1_b = (const float*)d_in[7];
    const float* fc2_w = (const float*)d_in[8];
    const float* fc2_b = (const float*)d_in[9];
    const float* fc3_w = (const float*)d_in[10];
    const float* fc3_b = (const float*)d_in[11];
    const float* fc4_w = (const float*)d_in[12];
    const float* fc4_b = (const float*)d_in[13];
    float* out = (float*)d_out;

    const unsigned EMB_SMEM = (HID0 * EMBED * 2 + HID0 + EMBED) * sizeof(float);
    static bool attr_set = false;
    if (!attr_set) {
        cudaFuncSetAttribute(k_emb_fc1, cudaFuncAttributeMaxDynamicSharedMemorySize,
                             EMB_SMEM);
        attr_set = true;
    }

    k_diag<<<N_NODES / 256, 256>>>(state);
    launch_pdl(k_matvec_fc1p, dim3(MV_BLOCKS + HID0), dim3(256), 0u,
               state, start, gc1_w, gc1_b, fc1_w);
    launch_pdl(k_emb_fc1, dim3(1), dim3(1024), EMB_SMEM,
               gc2_w, gc2_b, fc1_w, fc1_b);
    launch_pdl(k_fc2, dim3(HID1 / 8), dim3(256), 0u, fc2_w, fc2_b);
    launch_pdl(k_fc3, dim3(HID2 / 8), dim3(256), 0u, fc3_w, fc3_b);
    launch_pdl(k_fc4, dim3(ACTION / 8), dim3(256), 0u, fc4_w, fc4_b, out);
}